// round 10
// baseline (speedup 1.0000x reference)
#include <cuda_runtime.h>
#include <cuda_bf16.h>
#include <cstdint>

// Problem constants (fixed by setup_inputs)
#define HPM       8
#define NUM_PAGES 4096
#define PAGE_SIZE 16
#define DPM       128
#define MAX_SEQS  8
#define MAX_PPS   256
#define D4        (DPM / 4)                                    // 32 float4 per row
#define PAGES_ELEMS (2LL * HPM * NUM_PAGES * PAGE_SIZE * DPM)  // 134,217,728 floats
#define INNER_F4  (HPM * NUM_PAGES * PAGE_SIZE * D4)           // 1<<24 float4 per tensor
#define TOTAL_F4  (2u * INNER_F4)                              // 1<<25

#define NBLOCKS   512          // single wave guaranteed (needs 4 blocks/SM @ <=64 regs)
#define NTHREADS  256
#define TILES_PER_BLOCK 64     // 64 tiles x 1024 f4 = 65536 f4 per block
#define PAGES_PER_BLOCK 128    // 2 pages per tile

// ---------------------------------------------------------------------------
// Single fused kernel. Every block independently recomputes the first-fit
// allocation ranks (8MB aggregate L2-hit traffic, ~1us, parallel at t=0),
// stores the 128 entries it needs in smem, then streams its 64 tiles with
// the proven R8 copy body. Block 0 additionally emits the small outputs.
// No flags, no atomics, no cross-block sync: deterministic & graph-safe.
// ---------------------------------------------------------------------------
__global__ void __launch_bounds__(NTHREADS)
fused_pages_kernel(const float4* __restrict__ key,          // [1, S, H, D]
                   const float4* __restrict__ value,
                   const float4* __restrict__ key_pages,    // [H, P, PS, D]
                   const float4* __restrict__ value_pages,
                   const int*    __restrict__ page_indices,
                   const int*    __restrict__ seq_page_indices,
                   const int*    __restrict__ slot_p,
                   const int*    __restrict__ true_length_p,
                   float4* __restrict__ out,                 // [2, H, P, PS, D]
                   float*  __restrict__ out_pi,              // [4096]
                   float*  __restrict__ out_spi)             // [8, 256]
{
    __shared__ int s_base[8];
    __shared__ int s_blk[PAGES_PER_BLOCK];   // blk index (-1 = passthrough) for my 128 pages
    __shared__ int s_pob[MAX_PPS];           // page_of_block (block 0 only)

    const int tid  = threadIdx.x;
    const int lane = tid & 31;
    const int wrp  = tid >> 5;
    const unsigned bIdx = blockIdx.x;

    // ---------------- Prologue: redundant allocation scan ----------------
    const int4* pi4 = (const int4*)page_indices;
    int4 pv[4];
#pragma unroll
    for (int k = 0; k < 4; k++) pv[k] = __ldg(&pi4[tid * 4 + k]);
    const int tl_in = __ldg(true_length_p);

    int vals[16], fl[16];
    int cnt = 0;
#pragma unroll
    for (int k = 0; k < 4; k++) {
        vals[k*4+0] = pv[k].x; vals[k*4+1] = pv[k].y;
        vals[k*4+2] = pv[k].z; vals[k*4+3] = pv[k].w;
    }
#pragma unroll
    for (int j = 0; j < 16; j++) {
        int p = tid * 16 + j;
        fl[j] = (p >= 1) && (vals[j] == 0);
        cnt += fl[j];
    }

    // Warp inclusive scan of per-thread counts
    int incl = cnt;
#pragma unroll
    for (int off = 1; off < 32; off <<= 1) {
        int n = __shfl_up_sync(0xffffffffu, incl, off);
        if (lane >= off) incl += n;
    }
    if (lane == 31) s_base[wrp] = incl;
    __syncthreads();

    if (wrp == 0 && lane < 8) {
        int v = s_base[lane];
        int s = v;
#pragma unroll
        for (int off = 1; off < 8; off <<= 1) {
            int n = __shfl_up_sync(0xffu, s, off);
            if (lane >= off) s += n;
        }
        s_base[lane] = s - v;
    }
    __syncthreads();

    const int excl = s_base[wrp] + (incl - cnt);

    int nb = (tl_in + PAGE_SIZE - 1) / PAGE_SIZE;
    if (nb > MAX_PPS) nb = MAX_PPS;

    // My block's page window: [P0, P0+128)
    const unsigned P0 = PAGES_PER_BLOCK * (bIdx & 31u);
    const int owns = ((unsigned)(tid >> 3) == (bIdx & 31u));   // 8 threads own the window

    int run = excl;
#pragma unroll
    for (int j = 0; j < 16; j++) {
        int p = tid * 16 + j;
        int b = -1;
        if (fl[j]) {
            if (run < nb) {
                b = run;
                if (bIdx == 0) s_pob[run] = p;
            }
            run++;
        }
        if (owns) s_blk[(tid & 7) * 16 + j] = b;
        if (bIdx == 0) out_pi[p] = (b >= 0) ? 1.0f : (float)vals[j];
    }

    __syncthreads();   // s_blk (and s_pob for block 0) ready

    // Block 0: seq_page_indices output
    if (bIdx == 0) {
        const int slot = __ldg(slot_p);
#pragma unroll
        for (int k = 0; k < 8; k++) {
            int i = tid + k * 256;
            int r = i >> 8, c = i & 255;
            float v = (float)__ldg(&seq_page_indices[i]);
            if (r == slot && c < nb) v = (float)s_pob[c];
            out_spi[i] = v;
        }
    }

    // ---------------- Copy phase: 64 tiles, R8 body per tile ----------------
    const unsigned t = bIdx >> 8;                       // 0 = key, 1 = value (uniform)
    const unsigned h = (bIdx >> 5) & (HPM - 1);         // head (uniform)
    const float4* __restrict__ kv    = t ? value       : key;
    const float4* __restrict__ pages = t ? value_pages : key_pages;

    const unsigned blockBase = bIdx * (TILES_PER_BLOCK * 1024u);

    for (int tl = 0; tl < TILES_PER_BLOCK; tl++) {
        const int b0 = s_blk[2 * tl];
        const int b1 = s_blk[2 * tl + 1];
        const unsigned base = blockBase + tl * 1024u + tid;

        const float4* srcs[4];
#pragma unroll
        for (int j = 0; j < 4; j++) {
            unsigned idx = base + j * 256u;
            unsigned d4  = idx & (D4 - 1);
            unsigned row = (idx >> 5) & (PAGE_SIZE - 1);

            int b = (j < 2) ? b0 : b1;
            unsigned s    = (unsigned)b * PAGE_SIZE + row;
            unsigned offA = (s * HPM + h) * D4 + d4;     // key/value (transpose folded)
            unsigned offB = idx & (INNER_F4 - 1);        // pass-through pages
            srcs[j] = (b >= 0) ? (kv + offA) : (pages + offB);
        }

        float4 v4[4];
#pragma unroll
        for (int j = 0; j < 4; j++) v4[j] = __ldcs(srcs[j]);   // 4 back-to-back LDG.128.CS

#pragma unroll
        for (int j = 0; j < 4; j++) __stcs(&out[base + j * 256u], v4[j]);
    }
}

// ---------------------------------------------------------------------------
// Launch — ONE kernel node (single-node replay overhead ~5us vs ~12.6 for two).
// Inputs: key, value, key_pages, value_pages, page_indices, seq_page_indices,
//         slot, true_length
// Output: concat(pages[2,H,P,PS,D], page_indices[4096], seq_page_indices[2048])
// ---------------------------------------------------------------------------
extern "C" void kernel_launch(void* const* d_in, const int* in_sizes, int n_in,
                              void* d_out, int out_size)
{
    const float* key          = (const float*)d_in[0];
    const float* value        = (const float*)d_in[1];
    const float* key_pages    = (const float*)d_in[2];
    const float* value_pages  = (const float*)d_in[3];
    const int*   page_indices = (const int*)d_in[4];
    const int*   seq_page_ind = (const int*)d_in[5];
    const int*   slot         = (const int*)d_in[6];
    const int*   true_length  = (const int*)d_in[7];

    float* out_pages = (float*)d_out;
    float* out_pi    = out_pages + PAGES_ELEMS;
    float* out_spi   = out_pi + NUM_PAGES;

    fused_pages_kernel<<<NBLOCKS, NTHREADS>>>(
        (const float4*)key, (const float4*)value,
        (const float4*)key_pages, (const float4*)value_pages,
        page_indices, seq_page_ind, slot, true_length,
        (float4*)out_pages, out_pi, out_spi);
}

// round 11
// speedup vs baseline: 1.0984x; 1.0984x over previous
#include <cuda_runtime.h>
#include <cuda_bf16.h>
#include <cstdint>

// Problem constants (fixed by setup_inputs)
#define HPM       8
#define NUM_PAGES 4096
#define PAGE_SIZE 16
#define DPM       128
#define MAX_SEQS  8
#define MAX_PPS   256
#define D4        (DPM / 4)                                    // 32 float4 per row
#define PAGES_ELEMS (2LL * HPM * NUM_PAGES * PAGE_SIZE * DPM)  // 134,217,728 floats
#define INNER_F4  (HPM * NUM_PAGES * PAGE_SIZE * D4)           // 1<<24 float4 per tensor
#define TOTAL_F4  (2u * INNER_F4)                              // 1<<25

#define NBLOCKS         2048   // 2 balanced waves @ 7 blocks/SM
#define NTHREADS        256
#define TILES_PER_BLOCK 16     // 16 tiles x 1024 f4 = 16384 f4 per block
#define PAGES_PER_BLOCK 32     // 2 pages per tile

// ---------------------------------------------------------------------------
// Single fused kernel, occupancy-sized. Every block independently recomputes
// the first-fit allocation ranks (16KB L2-hit read + warp scan, ~1us, hidden
// after wave 1), keeps the 32 entries it needs in smem, then streams its 16
// tiles with the proven copy body. Block 0 also emits the small outputs.
// No flags, no atomics, no cross-block sync: deterministic & graph-safe.
// ---------------------------------------------------------------------------
__global__ void __launch_bounds__(NTHREADS, 7)
fused_pages_kernel(const float4* __restrict__ key,          // [1, S, H, D]
                   const float4* __restrict__ value,
                   const float4* __restrict__ key_pages,    // [H, P, PS, D]
                   const float4* __restrict__ value_pages,
                   const int*    __restrict__ page_indices,
                   const int*    __restrict__ seq_page_indices,
                   const int*    __restrict__ slot_p,
                   const int*    __restrict__ true_length_p,
                   float4* __restrict__ out,                 // [2, H, P, PS, D]
                   float*  __restrict__ out_pi,              // [4096]
                   float*  __restrict__ out_spi)             // [8, 256]
{
    __shared__ int s_base[8];
    __shared__ int s_blk[PAGES_PER_BLOCK];   // blk index (-1 = passthrough) for my 32 pages
    __shared__ int s_pob[MAX_PPS];           // page_of_block (block 0 only)

    const int tid  = threadIdx.x;
    const int lane = tid & 31;
    const int wrp  = tid >> 5;
    const unsigned bIdx = blockIdx.x;

    // ---------------- Prologue: redundant allocation scan ----------------
    const int4* pi4 = (const int4*)page_indices;
    int4 pv[4];
#pragma unroll
    for (int k = 0; k < 4; k++) pv[k] = __ldg(&pi4[tid * 4 + k]);
    const int tl_in = __ldg(true_length_p);

    int vals[16], fl[16];
    int cnt = 0;
#pragma unroll
    for (int k = 0; k < 4; k++) {
        vals[k*4+0] = pv[k].x; vals[k*4+1] = pv[k].y;
        vals[k*4+2] = pv[k].z; vals[k*4+3] = pv[k].w;
    }
#pragma unroll
    for (int j = 0; j < 16; j++) {
        int p = tid * 16 + j;
        fl[j] = (p >= 1) && (vals[j] == 0);
        cnt += fl[j];
    }

    // Warp inclusive scan of per-thread counts
    int incl = cnt;
#pragma unroll
    for (int off = 1; off < 32; off <<= 1) {
        int n = __shfl_up_sync(0xffffffffu, incl, off);
        if (lane >= off) incl += n;
    }
    if (lane == 31) s_base[wrp] = incl;
    __syncthreads();

    if (wrp == 0 && lane < 8) {
        int v = s_base[lane];
        int s = v;
#pragma unroll
        for (int off = 1; off < 8; off <<= 1) {
            int n = __shfl_up_sync(0xffu, s, off);
            if (lane >= off) s += n;
        }
        s_base[lane] = s - v;
    }
    __syncthreads();

    const int excl = s_base[wrp] + (incl - cnt);

    int nb = (tl_in + PAGE_SIZE - 1) / PAGE_SIZE;
    if (nb > MAX_PPS) nb = MAX_PPS;

    // My block's page window: [32*(bIdx&127), +32); owner threads: tid>>1 == bIdx&127
    const int owns = ((unsigned)(tid >> 1) == (bIdx & 127u));

    int run = excl;
#pragma unroll
    for (int j = 0; j < 16; j++) {
        int p = tid * 16 + j;
        int b = -1;
        if (fl[j]) {
            if (run < nb) {
                b = run;
                if (bIdx == 0) s_pob[run] = p;
            }
            run++;
        }
        if (owns) s_blk[(tid & 1) * 16 + j] = b;
        if (bIdx == 0) out_pi[p] = (b >= 0) ? 1.0f : (float)vals[j];
    }

    __syncthreads();   // s_blk (and s_pob for block 0) ready

    // Block 0: seq_page_indices output
    if (bIdx == 0) {
        const int slot = __ldg(slot_p);
#pragma unroll
        for (int k = 0; k < 8; k++) {
            int i = tid + k * 256;
            int r = i >> 8, c = i & 255;
            float v = (float)__ldg(&seq_page_indices[i]);
            if (r == slot && c < nb) v = (float)s_pob[c];
            out_spi[i] = v;
        }
    }

    // ---------------- Copy phase: 16 tiles, proven body per tile ----------------
    const unsigned t = bIdx >> 10;                      // 0 = key, 1 = value (uniform)
    const unsigned h = (bIdx >> 7) & (HPM - 1);         // head (uniform)
    const float4* __restrict__ kv    = t ? value       : key;
    const float4* __restrict__ pages = t ? value_pages : key_pages;

    const unsigned blockBase = bIdx * (TILES_PER_BLOCK * 1024u);

#pragma unroll 2
    for (int tl = 0; tl < TILES_PER_BLOCK; tl++) {
        const int b0 = s_blk[2 * tl];
        const int b1 = s_blk[2 * tl + 1];
        const unsigned base = blockBase + tl * 1024u + tid;

        const float4* srcs[4];
#pragma unroll
        for (int j = 0; j < 4; j++) {
            unsigned idx = base + j * 256u;
            unsigned d4  = idx & (D4 - 1);
            unsigned row = (idx >> 5) & (PAGE_SIZE - 1);

            int b = (j < 2) ? b0 : b1;
            unsigned s    = (unsigned)b * PAGE_SIZE + row;
            unsigned offA = (s * HPM + h) * D4 + d4;     // key/value (transpose folded)
            unsigned offB = idx & (INNER_F4 - 1);        // pass-through pages
            srcs[j] = (b >= 0) ? (kv + offA) : (pages + offB);
        }

        float4 v4[4];
#pragma unroll
        for (int j = 0; j < 4; j++) v4[j] = __ldcs(srcs[j]);   // 4 back-to-back LDG.128.CS

#pragma unroll
        for (int j = 0; j < 4; j++) __stcs(&out[base + j * 256u], v4[j]);
    }
}

// ---------------------------------------------------------------------------
// Launch — ONE kernel node.
// Inputs: key, value, key_pages, value_pages, page_indices, seq_page_indices,
//         slot, true_length
// Output: concat(pages[2,H,P,PS,D], page_indices[4096], seq_page_indices[2048])
// ---------------------------------------------------------------------------
extern "C" void kernel_launch(void* const* d_in, const int* in_sizes, int n_in,
                              void* d_out, int out_size)
{
    const float* key          = (const float*)d_in[0];
    const float* value        = (const float*)d_in[1];
    const float* key_pages    = (const float*)d_in[2];
    const float* value_pages  = (const float*)d_in[3];
    const int*   page_indices = (const int*)d_in[4];
    const int*   seq_page_ind = (const int*)d_in[5];
    const int*   slot         = (const int*)d_in[6];
    const int*   true_length  = (const int*)d_in[7];

    float* out_pages = (float*)d_out;
    float* out_pi    = out_pages + PAGES_ELEMS;
    float* out_spi   = out_pi + NUM_PAGES;

    fused_pages_kernel<<<NBLOCKS, NTHREADS>>>(
        (const float4*)key, (const float4*)value,
        (const float4*)key_pages, (const float4*)value_pages,
        page_indices, seq_page_ind, slot, true_length,
        (float4*)out_pages, out_pi, out_spi);
}